// round 1
// baseline (speedup 1.0000x reference)
#include <cuda_runtime.h>
#include <math.h>

// graphConvNet: two 8192-node GCN embeds + tiny combine/MLP head.
// Rewrite: (An@X)@W == An@(X@W); An = d*A*d with d = rsqrt(diag(D)).
// Pipeline per graph g:
//   d[i] = rsqrt(D[i,i])
//   Y = d .* (H @ W1)                      [8192 x 64]
//   X = relu(d .* (A @ Y))                 prop<64>
//   Y = d .* (X @ W2)                      [8192 x 32]
//   X = relu(d .* (A @ Y))                 prop<32>
//   Y = d .* (X @ W3)                      [8192 x 16]
//   X = relu(d .* (A @ Y))                 prop<16>
//   emb[g] = mean(X, axis=0)               [16]
// final: bilinear + linear + 3-layer MLP -> scalar.

constexpr int N = 8192;

__device__ float g_d[2][N];
__device__ float g_emb[32];
__device__ __align__(16) float g_Y[(size_t)N * 64];
__device__ __align__(16) float g_X[(size_t)N * 64];

__device__ __forceinline__ void fma2(unsigned long long& d,
                                     unsigned long long a,
                                     unsigned long long b) {
    asm("fma.rn.f32x2 %0, %1, %2, %0;" : "+l"(d) : "l"(a), "l"(b));
}

__device__ __forceinline__ unsigned long long bcast2(float z) {
    unsigned long long r;
    asm("mov.b64 %0, {%1, %1};" : "=l"(r) : "f"(z));
    return r;
}

__device__ __forceinline__ float lo32(unsigned long long v) {
    return __uint_as_float((unsigned int)(v & 0xffffffffULL));
}
__device__ __forceinline__ float hi32(unsigned long long v) {
    return __uint_as_float((unsigned int)(v >> 32));
}

// ---------------------------------------------------------------------------
// d = rsqrt(diag(D)); also zero this graph's embedding accumulator.
__global__ void diag_kernel(const float* __restrict__ Dm, int g) {
    int i = blockIdx.x * 256 + threadIdx.x;
    if (i < N) g_d[g][i] = rsqrtf(Dm[(size_t)i * (N + 1)]);
    if (blockIdx.x == 0 && threadIdx.x < 16) g_emb[g * 16 + threadIdx.x] = 0.0f;
}

// ---------------------------------------------------------------------------
// g_Y[r, c] = d[r] * sum_t src[r, t] * W[t, c]     (TIN -> TOUT)
// src = Xin param (H) if SRC_IS_PARAM else g_X.
template <int TIN, int TOUT, bool SRC_IS_PARAM>
__global__ __launch_bounds__(256) void wmul_kernel(const float* __restrict__ Xin,
                                                   const float* __restrict__ W,
                                                   int g) {
    __shared__ float Ws[TIN * TOUT];
    for (int i = threadIdx.x; i < TIN * TOUT; i += 256) Ws[i] = W[i];
    __syncthreads();

    const float* src;
    if constexpr (SRC_IS_PARAM) src = Xin; else src = g_X;

    const int total = N * TOUT;
    for (int idx = blockIdx.x * 256 + threadIdx.x; idx < total;
         idx += gridDim.x * 256) {
        int r = idx / TOUT;
        int c = idx - r * TOUT;
        const float* xr = src + (size_t)r * TIN;
        float acc = 0.0f;
#pragma unroll
        for (int t = 0; t < TIN; t += 4) {
            float4 xv = *(const float4*)(xr + t);
            acc += xv.x * Ws[(t + 0) * TOUT + c];
            acc += xv.y * Ws[(t + 1) * TOUT + c];
            acc += xv.z * Ws[(t + 2) * TOUT + c];
            acc += xv.w * Ws[(t + 3) * TOUT + c];
        }
        g_Y[(size_t)r * TOUT + c] = g_d[g][r] * acc;
    }
}

// ---------------------------------------------------------------------------
// g_X[i, c] = relu(d[i] * sum_j A[i, j] * g_Y[j, c]),  K columns.
// BM=64 rows/block, BK=32 k-chunk, 256 threads (16x16), TM=4 (2 f32x2 pairs),
// TN=K/16. Inner product uses packed fma.rn.f32x2 (2x FFMA throughput).
template <int K>
__global__ __launch_bounds__(256) void prop_kernel(const float* __restrict__ A,
                                                   int g) {
    constexpr int BM = 64;
    constexpr int BK = 32;
    constexpr int TN = K / 16;

    __shared__ __align__(16) float As[BK][BM + 2];  // transposed: As[kk][row]
    __shared__ __align__(16) float Zs[BK][K];

    const int tid = threadIdx.x;
    const int tx = tid & 15;   // col group
    const int ty = tid >> 4;   // row group (0..15), 4 rows each
    const int rowBase = blockIdx.x * BM;

    unsigned long long acc[2][TN];
#pragma unroll
    for (int p = 0; p < 2; ++p)
#pragma unroll
        for (int t = 0; t < TN; ++t) acc[p][t] = 0ULL;  // {0.f, 0.f}

    const float* Abase = A + (size_t)rowBase * N;

    // A-tile loader mapping: 8 floats (2x float4) per thread.
    const int lr = tid >> 3;          // 0..31
    const int lc = (tid & 7) * 4;     // 0,4,...,28

    for (int j0 = 0; j0 < N; j0 += BK) {
        // Load A tile [64 x 32] -> transposed shared.
#pragma unroll
        for (int it = 0; it < 2; ++it) {
            int rr = lr + it * 32;
            float4 v = *(const float4*)(Abase + (size_t)rr * N + j0 + lc);
            As[lc + 0][rr] = v.x;
            As[lc + 1][rr] = v.y;
            As[lc + 2][rr] = v.z;
            As[lc + 3][rr] = v.w;
        }
        // Load Z tile [32 x K] (contiguous in g_Y).
        {
            const float* Z = g_Y + (size_t)j0 * K;
            for (int i = tid * 4; i < BK * K; i += 256 * 4) {
                *(float4*)(&Zs[0][0] + i) = *(const float4*)(Z + i);
            }
        }
        __syncthreads();

#pragma unroll
        for (int kk = 0; kk < BK; ++kk) {
            unsigned long long a01 =
                *(const unsigned long long*)&As[kk][ty * 4];
            unsigned long long a23 =
                *(const unsigned long long*)&As[kk][ty * 4 + 2];
            float zf[TN];
            if constexpr (TN == 4) {
                float4 v = *(const float4*)&Zs[kk][tx * 4];
                zf[0] = v.x; zf[1] = v.y; zf[2] = v.z; zf[3] = v.w;
            } else if constexpr (TN == 2) {
                float2 v = *(const float2*)&Zs[kk][tx * 2];
                zf[0] = v.x; zf[1] = v.y;
            } else {
                zf[0] = Zs[kk][tx];
            }
#pragma unroll
            for (int t = 0; t < TN; ++t) {
                unsigned long long zz = bcast2(zf[t]);
                fma2(acc[0][t], a01, zz);
                fma2(acc[1][t], a23, zz);
            }
        }
        __syncthreads();
    }

    // Epilogue: scale by d[i], relu, store.
    const int r0 = rowBase + ty * 4;
#pragma unroll
    for (int p = 0; p < 2; ++p) {
        float dlo = g_d[g][r0 + 2 * p + 0];
        float dhi = g_d[g][r0 + 2 * p + 1];
#pragma unroll
        for (int t = 0; t < TN; ++t) {
            int col = tx * TN + t;
            float vlo = fmaxf(dlo * lo32(acc[p][t]), 0.0f);
            float vhi = fmaxf(dhi * hi32(acc[p][t]), 0.0f);
            g_X[(size_t)(r0 + 2 * p + 0) * K + col] = vlo;
            g_X[(size_t)(r0 + 2 * p + 1) * K + col] = vhi;
        }
    }
}

// ---------------------------------------------------------------------------
// emb[g] += column means of g_X[8192 x 16].
__global__ void mean_kernel(int g) {
    __shared__ float sm[256];
    const int base = blockIdx.x * 128;
    const int c = threadIdx.x & 15;
    const int rg = threadIdx.x >> 4;
    float s = 0.0f;
    for (int r = rg; r < 128; r += 16) s += g_X[(size_t)(base + r) * 16 + c];
    sm[threadIdx.x] = s;
    __syncthreads();
    for (int off = 128; off >= 16; off >>= 1) {
        if (threadIdx.x < off) sm[threadIdx.x] += sm[threadIdx.x + off];
        __syncthreads();
    }
    if (threadIdx.x < 16)
        atomicAdd(&g_emb[g * 16 + threadIdx.x], sm[threadIdx.x] * (1.0f / N));
}

// ---------------------------------------------------------------------------
// combine + MLP head -> scalar.
__global__ void final_kernel(const float* __restrict__ cw1,
                             const float* __restrict__ cw2,
                             const float* __restrict__ cbias,
                             const float* __restrict__ fw1,
                             const float* __restrict__ fb1,
                             const float* __restrict__ fw2,
                             const float* __restrict__ fb2,
                             const float* __restrict__ fw3,
                             const float* __restrict__ fb3,
                             float* __restrict__ out) {
    __shared__ float z[16];
    const int k = threadIdx.x;
    if (k < 16) {
        float r = 0.0f;
        for (int i = 0; i < 16; ++i) {
            float xi = g_emb[i];
            for (int j = 0; j < 16; ++j)
                r += xi * cw1[(i * 16 + j) * 16 + k] * g_emb[16 + j];
        }
        float p = 0.0f;
        for (int t = 0; t < 32; ++t) p += cw2[k * 32 + t] * g_emb[t];
        z[k] = fmaxf(r + p + cbias[k], 0.0f);
    }
    __syncthreads();
    if (k == 0) {
        float z1[8];
        for (int a = 0; a < 8; ++a) {
            float s = fb1[a];
            for (int t = 0; t < 16; ++t) s += z[t] * fw1[a * 16 + t];
            z1[a] = fmaxf(s, 0.0f);
        }
        float z2[4];
        for (int b = 0; b < 4; ++b) {
            float s = fb2[b];
            for (int a = 0; a < 8; ++a) s += z1[a] * fw2[b * 8 + a];
            z2[b] = fmaxf(s, 0.0f);
        }
        float s = fb3[0];
        for (int b = 0; b < 4; ++b) s += z2[b] * fw3[b];
        out[0] = fmaxf(s, 0.0f);
    }
}

// ---------------------------------------------------------------------------
extern "C" void kernel_launch(void* const* d_in, const int* in_sizes, int n_in,
                              void* d_out, int out_size) {
    (void)in_sizes; (void)n_in; (void)out_size;
    const float* A[2] = {(const float*)d_in[0], (const float*)d_in[3]};
    const float* Dm[2] = {(const float*)d_in[1], (const float*)d_in[4]};
    const float* H[2] = {(const float*)d_in[2], (const float*)d_in[5]};
    const float* W1 = (const float*)d_in[6];
    const float* W2 = (const float*)d_in[7];
    const float* W3 = (const float*)d_in[8];
    const float* cw1 = (const float*)d_in[9];
    const float* cw2 = (const float*)d_in[10];
    const float* cbias = (const float*)d_in[11];
    const float* fw1 = (const float*)d_in[12];
    const float* fb1 = (const float*)d_in[13];
    const float* fw2 = (const float*)d_in[14];
    const float* fb2 = (const float*)d_in[15];
    const float* fw3 = (const float*)d_in[16];
    const float* fb3 = (const float*)d_in[17];

    for (int g = 0; g < 2; ++g) {
        diag_kernel<<<N / 256, 256>>>(Dm[g], g);
        wmul_kernel<128, 64, true><<<256, 256>>>(H[g], W1, g);
        prop_kernel<64><<<N / 64, 256>>>(A[g], g);
        wmul_kernel<64, 32, false><<<256, 256>>>(nullptr, W2, g);
        prop_kernel<32><<<N / 64, 256>>>(A[g], g);
        wmul_kernel<32, 16, false><<<256, 256>>>(nullptr, W3, g);
        prop_kernel<16><<<N / 64, 256>>>(A[g], g);
        mean_kernel<<<64, 256>>>(g);
    }
    final_kernel<<<1, 32>>>(cw1, cw2, cbias, fw1, fb1, fw2, fb2, fw3, fb3,
                            (float*)d_out);
}

// round 2
// speedup vs baseline: 1.0003x; 1.0003x over previous
#include <cuda_runtime.h>
#include <math.h>

// graphConvNet: two 8192-node GCN embeds + tiny combine/MLP head.
// Rewrite: (An@X)@W == An@(X@W); An = d*A*d with d = rsqrt(diag(D)).
// Pipeline per graph g:
//   d[i] = rsqrt(D[i,i])
//   Y = d .* (H @ W1)                      [8192 x 64]
//   X = relu(d .* (A @ Y))                 prop<64>
//   Y = d .* (X @ W2)                      [8192 x 32]
//   X = relu(d .* (A @ Y))                 prop<32>
//   Y = d .* (X @ W3)                      [8192 x 16]
//   X = relu(d .* (A @ Y))                 prop<16>
//   emb[g] = mean(X, axis=0)               [16]
// final: bilinear + linear + 3-layer MLP -> scalar.

constexpr int N = 8192;

__device__ float g_d[2][N];
__device__ float g_emb[32];
__device__ __align__(16) float g_Y[(size_t)N * 64];
__device__ __align__(16) float g_X[(size_t)N * 64];

__device__ __forceinline__ void fma2(unsigned long long& d,
                                     unsigned long long a,
                                     unsigned long long b) {
    asm("fma.rn.f32x2 %0, %1, %2, %0;" : "+l"(d) : "l"(a), "l"(b));
}

__device__ __forceinline__ unsigned long long bcast2(float z) {
    unsigned long long r;
    asm("mov.b64 %0, {%1, %1};" : "=l"(r) : "f"(z));
    return r;
}

__device__ __forceinline__ float lo32(unsigned long long v) {
    return __uint_as_float((unsigned int)(v & 0xffffffffULL));
}
__device__ __forceinline__ float hi32(unsigned long long v) {
    return __uint_as_float((unsigned int)(v >> 32));
}

// ---------------------------------------------------------------------------
// d = rsqrt(diag(D)); also zero this graph's embedding accumulator.
__global__ void diag_kernel(const float* __restrict__ Dm, int g) {
    int i = blockIdx.x * 256 + threadIdx.x;
    if (i < N) g_d[g][i] = rsqrtf(Dm[(size_t)i * (N + 1)]);
    if (blockIdx.x == 0 && threadIdx.x < 16) g_emb[g * 16 + threadIdx.x] = 0.0f;
}

// ---------------------------------------------------------------------------
// g_Y[r, c] = d[r] * sum_t src[r, t] * W[t, c]     (TIN -> TOUT)
// src = Xin param (H) if SRC_IS_PARAM else g_X.
template <int TIN, int TOUT, bool SRC_IS_PARAM>
__global__ __launch_bounds__(256) void wmul_kernel(const float* __restrict__ Xin,
                                                   const float* __restrict__ W,
                                                   int g) {
    __shared__ float Ws[TIN * TOUT];
    for (int i = threadIdx.x; i < TIN * TOUT; i += 256) Ws[i] = W[i];
    __syncthreads();

    const float* src;
    if constexpr (SRC_IS_PARAM) src = Xin; else src = g_X;

    const int total = N * TOUT;
    for (int idx = blockIdx.x * 256 + threadIdx.x; idx < total;
         idx += gridDim.x * 256) {
        int r = idx / TOUT;
        int c = idx - r * TOUT;
        const float* xr = src + (size_t)r * TIN;
        float acc = 0.0f;
#pragma unroll
        for (int t = 0; t < TIN; t += 4) {
            float4 xv = *(const float4*)(xr + t);
            acc += xv.x * Ws[(t + 0) * TOUT + c];
            acc += xv.y * Ws[(t + 1) * TOUT + c];
            acc += xv.z * Ws[(t + 2) * TOUT + c];
            acc += xv.w * Ws[(t + 3) * TOUT + c];
        }
        g_Y[(size_t)r * TOUT + c] = g_d[g][r] * acc;
    }
}

// ---------------------------------------------------------------------------
// g_X[i, c] = relu(d[i] * sum_j A[i, j] * g_Y[j, c]),  K columns.
// BM=64 rows/block, BK=32 k-chunk, 256 threads (16x16), TM=4 (2 f32x2 pairs),
// TN=K/16. Inner product uses packed fma.rn.f32x2 (2x FFMA throughput).
template <int K>
__global__ __launch_bounds__(256) void prop_kernel(const float* __restrict__ A,
                                                   int g) {
    constexpr int BM = 64;
    constexpr int BK = 32;
    constexpr int TN = K / 16;

    __shared__ __align__(16) float As[BK][BM + 2];  // transposed: As[kk][row]
    __shared__ __align__(16) float Zs[BK][K];

    const int tid = threadIdx.x;
    const int tx = tid & 15;   // col group
    const int ty = tid >> 4;   // row group (0..15), 4 rows each
    const int rowBase = blockIdx.x * BM;

    unsigned long long acc[2][TN];
#pragma unroll
    for (int p = 0; p < 2; ++p)
#pragma unroll
        for (int t = 0; t < TN; ++t) acc[p][t] = 0ULL;  // {0.f, 0.f}

    const float* Abase = A + (size_t)rowBase * N;

    // A-tile loader mapping: 8 floats (2x float4) per thread.
    const int lr = tid >> 3;          // 0..31
    const int lc = (tid & 7) * 4;     // 0,4,...,28

    for (int j0 = 0; j0 < N; j0 += BK) {
        // Load A tile [64 x 32] -> transposed shared.
#pragma unroll
        for (int it = 0; it < 2; ++it) {
            int rr = lr + it * 32;
            float4 v = *(const float4*)(Abase + (size_t)rr * N + j0 + lc);
            As[lc + 0][rr] = v.x;
            As[lc + 1][rr] = v.y;
            As[lc + 2][rr] = v.z;
            As[lc + 3][rr] = v.w;
        }
        // Load Z tile [32 x K] (contiguous in g_Y).
        {
            const float* Z = g_Y + (size_t)j0 * K;
            for (int i = tid * 4; i < BK * K; i += 256 * 4) {
                *(float4*)(&Zs[0][0] + i) = *(const float4*)(Z + i);
            }
        }
        __syncthreads();

#pragma unroll
        for (int kk = 0; kk < BK; ++kk) {
            unsigned long long a01 =
                *(const unsigned long long*)&As[kk][ty * 4];
            unsigned long long a23 =
                *(const unsigned long long*)&As[kk][ty * 4 + 2];
            float zf[TN];
            if constexpr (TN == 4) {
                float4 v = *(const float4*)&Zs[kk][tx * 4];
                zf[0] = v.x; zf[1] = v.y; zf[2] = v.z; zf[3] = v.w;
            } else if constexpr (TN == 2) {
                float2 v = *(const float2*)&Zs[kk][tx * 2];
                zf[0] = v.x; zf[1] = v.y;
            } else {
                zf[0] = Zs[kk][tx];
            }
#pragma unroll
            for (int t = 0; t < TN; ++t) {
                unsigned long long zz = bcast2(zf[t]);
                fma2(acc[0][t], a01, zz);
                fma2(acc[1][t], a23, zz);
            }
        }
        __syncthreads();
    }

    // Epilogue: scale by d[i], relu, store.
    const int r0 = rowBase + ty * 4;
#pragma unroll
    for (int p = 0; p < 2; ++p) {
        float dlo = g_d[g][r0 + 2 * p + 0];
        float dhi = g_d[g][r0 + 2 * p + 1];
#pragma unroll
        for (int t = 0; t < TN; ++t) {
            int col = tx * TN + t;
            float vlo = fmaxf(dlo * lo32(acc[p][t]), 0.0f);
            float vhi = fmaxf(dhi * hi32(acc[p][t]), 0.0f);
            g_X[(size_t)(r0 + 2 * p + 0) * K + col] = vlo;
            g_X[(size_t)(r0 + 2 * p + 1) * K + col] = vhi;
        }
    }
}

// ---------------------------------------------------------------------------
// emb[g] += column means of g_X[8192 x 16].
__global__ void mean_kernel(int g) {
    __shared__ float sm[256];
    const int base = blockIdx.x * 128;
    const int c = threadIdx.x & 15;
    const int rg = threadIdx.x >> 4;
    float s = 0.0f;
    for (int r = rg; r < 128; r += 16) s += g_X[(size_t)(base + r) * 16 + c];
    sm[threadIdx.x] = s;
    __syncthreads();
    for (int off = 128; off >= 16; off >>= 1) {
        if (threadIdx.x < off) sm[threadIdx.x] += sm[threadIdx.x + off];
        __syncthreads();
    }
    if (threadIdx.x < 16)
        atomicAdd(&g_emb[g * 16 + threadIdx.x], sm[threadIdx.x] * (1.0f / N));
}

// ---------------------------------------------------------------------------
// combine + MLP head -> scalar.
__global__ void final_kernel(const float* __restrict__ cw1,
                             const float* __restrict__ cw2,
                             const float* __restrict__ cbias,
                             const float* __restrict__ fw1,
                             const float* __restrict__ fb1,
                             const float* __restrict__ fw2,
                             const float* __restrict__ fb2,
                             const float* __restrict__ fw3,
                             const float* __restrict__ fb3,
                             float* __restrict__ out) {
    __shared__ float z[16];
    const int k = threadIdx.x;
    if (k < 16) {
        float r = 0.0f;
        for (int i = 0; i < 16; ++i) {
            float xi = g_emb[i];
            for (int j = 0; j < 16; ++j)
                r += xi * cw1[(i * 16 + j) * 16 + k] * g_emb[16 + j];
        }
        float p = 0.0f;
        for (int t = 0; t < 32; ++t) p += cw2[k * 32 + t] * g_emb[t];
        z[k] = fmaxf(r + p + cbias[k], 0.0f);
    }
    __syncthreads();
    if (k == 0) {
        float z1[8];
        for (int a = 0; a < 8; ++a) {
            float s = fb1[a];
            for (int t = 0; t < 16; ++t) s += z[t] * fw1[a * 16 + t];
            z1[a] = fmaxf(s, 0.0f);
        }
        float z2[4];
        for (int b = 0; b < 4; ++b) {
            float s = fb2[b];
            for (int a = 0; a < 8; ++a) s += z1[a] * fw2[b * 8 + a];
            z2[b] = fmaxf(s, 0.0f);
        }
        float s = fb3[0];
        for (int b = 0; b < 4; ++b) s += z2[b] * fw3[b];
        out[0] = fmaxf(s, 0.0f);
    }
}

// ---------------------------------------------------------------------------
extern "C" void kernel_launch(void* const* d_in, const int* in_sizes, int n_in,
                              void* d_out, int out_size) {
    (void)in_sizes; (void)n_in; (void)out_size;
    const float* A[2] = {(const float*)d_in[0], (const float*)d_in[3]};
    const float* Dm[2] = {(const float*)d_in[1], (const float*)d_in[4]};
    const float* H[2] = {(const float*)d_in[2], (const float*)d_in[5]};
    const float* W1 = (const float*)d_in[6];
    const float* W2 = (const float*)d_in[7];
    const float* W3 = (const float*)d_in[8];
    const float* cw1 = (const float*)d_in[9];
    const float* cw2 = (const float*)d_in[10];
    const float* cbias = (const float*)d_in[11];
    const float* fw1 = (const float*)d_in[12];
    const float* fb1 = (const float*)d_in[13];
    const float* fw2 = (const float*)d_in[14];
    const float* fb2 = (const float*)d_in[15];
    const float* fw3 = (const float*)d_in[16];
    const float* fb3 = (const float*)d_in[17];

    for (int g = 0; g < 2; ++g) {
        diag_kernel<<<N / 256, 256>>>(Dm[g], g);
        wmul_kernel<128, 64, true><<<256, 256>>>(H[g], W1, g);
        prop_kernel<64><<<N / 64, 256>>>(A[g], g);
        wmul_kernel<64, 32, false><<<256, 256>>>(nullptr, W2, g);
        prop_kernel<32><<<N / 64, 256>>>(A[g], g);
        wmul_kernel<32, 16, false><<<256, 256>>>(nullptr, W3, g);
        prop_kernel<16><<<N / 64, 256>>>(A[g], g);
        mean_kernel<<<64, 256>>>(g);
    }
    final_kernel<<<1, 32>>>(cw1, cw2, cbias, fw1, fb1, fw2, fb2, fw3, fb3,
                            (float*)d_out);
}

// round 4
// speedup vs baseline: 1.6940x; 1.6935x over previous
#include <cuda_runtime.h>
#include <math.h>

// graphConvNet: two 8192-node GCNs + tiny head.
// (An@X)@W == An@(X@W);  An = d*A*d, d = rsqrt(diag(D)).
// Per graph: Y=d.*(H@W1) [64] -> prop64 (fused *W2*d) -> [32]
//            -> prop32 (fused *W3*d) -> [16] -> prop16 (+col-sum partials)
// final: reduce partials -> emb -> bilinear+MLP head -> scalar.
//
// prop inner product: k-split fma.rn.f32x2 — both operands are natural
// 8B k-pairs (A via cp.async row-major; Z transposed in smem w/ XOR swizzle).

constexpr int N = 8192;
constexpr int BM = 32;
constexpr int BK = 64;
constexpr int NTILE = N / BK;   // 128
constexpr int GRIDX = N / BM;   // 256

__device__ float g_d[2][N];
__device__ __align__(16) float g_Y[2][(size_t)N * 64];
__device__ __align__(16) float g_Zb[2][(size_t)N * 32];
__device__ float g_part[2][GRIDX][16];

typedef unsigned long long u64;

__device__ __forceinline__ void fma2(u64& d, u64 a, u64 b) {
    asm("fma.rn.f32x2 %0, %1, %2, %0;" : "+l"(d) : "l"(a), "l"(b));
}
__device__ __forceinline__ float lo32(u64 v) { return __uint_as_float((unsigned)v); }
__device__ __forceinline__ float hi32(u64 v) { return __uint_as_float((unsigned)(v >> 32)); }

__device__ __forceinline__ void cp16(unsigned dst, const float* src) {
    asm volatile("cp.async.cg.shared.global [%0], [%1], 16;" :: "r"(dst), "l"(src));
}
__device__ __forceinline__ void cp_commit() { asm volatile("cp.async.commit_group;"); }
__device__ __forceinline__ void cp_wait0()  { asm volatile("cp.async.wait_group 0;"); }

// ---------------------------------------------------------------------------
__global__ void diag_kernel(const float* __restrict__ D0,
                            const float* __restrict__ D1) {
    const int g = blockIdx.y;
    const float* Dm = g ? D1 : D0;
    int i = blockIdx.x * 256 + threadIdx.x;
    if (i < N) g_d[g][i] = rsqrtf(Dm[(size_t)i * (N + 1)]);
}

// ---------------------------------------------------------------------------
// g_Y[g][r, 0:64] = d[r] * (H[r, 0:128] @ W1[128x64])
constexpr int BMH = 16;
__global__ __launch_bounds__(256) void wmulH_kernel(const float* __restrict__ H0,
                                                    const float* __restrict__ H1,
                                                    const float* __restrict__ W1) {
    __shared__ float Hs[BMH][128];
    __shared__ float W1s[128 * 64];
    const int tid = threadIdx.x;
    const int g = blockIdx.y;
    const float* Hg = g ? H1 : H0;
    const int rowBase = blockIdx.x * BMH;

    for (int i = tid; i < 2048; i += 256)
        ((float4*)W1s)[i] = ((const float4*)W1)[i];
    for (int i = tid; i < 512; i += 256) {
        int r = i >> 5, c4 = (i & 31) * 4;
        *(float4*)&Hs[r][c4] = *(const float4*)(Hg + (size_t)(rowBase + r) * 128 + c4);
    }
    __syncthreads();

    const int r = tid >> 4;          // 0..15
    const int co = (tid & 15) * 4;   // 0..60
    float a0 = 0, a1 = 0, a2 = 0, a3 = 0;
#pragma unroll 16
    for (int t = 0; t < 128; ++t) {
        float x = Hs[r][t];
        float4 w = *(const float4*)&W1s[t * 64 + co];
        a0 += x * w.x; a1 += x * w.y; a2 += x * w.z; a3 += x * w.w;
    }
    float dr = g_d[g][rowBase + r];
    float4 o = {dr * a0, dr * a1, dr * a2, dr * a3};
    *(float4*)(g_Y[g] + (size_t)(rowBase + r) * 64 + co) = o;
}

// ---------------------------------------------------------------------------
// X = relu(d .* (A @ Yin));  if KO>0: out = d .* (X @ W)  else col-sum partials.
// SRC=0: Yin=g_Y, out=g_Zb ; SRC=1: Yin=g_Zb, out=g_Y.
template <int K, int KO, int SRC>
__global__ __launch_bounds__(256, 4) void prop_kernel(
    const float* __restrict__ A0, const float* __restrict__ A1,
    const float* __restrict__ W) {
    constexpr int TNc = K / 16;                        // col-groups per thread
    constexpr int SH = (TNc == 4) ? 2 : (TNc == 2 ? 1 : 0);
    constexpr int NZ4 = (BK * K) / 1024;               // float4 loads per thread
    constexpr int KD4 = K / 4;

    __shared__ float As[2][BM][BK];                    // natural layout (cp.async)
    __shared__ float Zst[2][K][BK];                    // transposed + swizzled

    const int tid = threadIdx.x;
    const int g = blockIdx.y;
    const int tx = tid & 15;
    const int ty = tid >> 4;
    const int rowBase = blockIdx.x * BM;

    const float* __restrict__ Ag = g ? A1 : A0;
    const float* __restrict__ Yg = SRC ? g_Zb[g] : g_Y[g];
    const float* Abase = Ag + (size_t)rowBase * N;

    // A tile: 32x64 floats = 512 x 16B; 2 chunks/thread.
    const int ar = tid >> 4;
    const int ac = (tid & 15) * 4;
    unsigned adst[2][2];
#pragma unroll
    for (int bb = 0; bb < 2; ++bb)
#pragma unroll
        for (int i = 0; i < 2; ++i)
            adst[bb][i] = (unsigned)__cvta_generic_to_shared(&As[bb][ar + 16 * i][ac]);
    const float* asrc[2];
    asrc[0] = Abase + (size_t)ar * N + ac;
    asrc[1] = Abase + (size_t)(ar + 16) * N + ac;

    int zj[NZ4], zc4[NZ4];
#pragma unroll
    for (int i = 0; i < NZ4; ++i) {
        int f4 = i * 256 + tid;
        zj[i] = f4 / KD4;
        zc4[i] = (f4 % KD4) * 4;
    }

    u64 acc[2][TNc];
#pragma unroll
    for (int i = 0; i < 2; ++i)
#pragma unroll
        for (int j = 0; j < TNc; ++j) acc[i][j] = 0ULL;

    float4 zr[NZ4];

    // prologue: prefetch tile 0
#pragma unroll
    for (int i = 0; i < 2; ++i) cp16(adst[0][i], asrc[i]);
    cp_commit();
#pragma unroll
    for (int i = 0; i < NZ4; ++i)
        zr[i] = *(const float4*)(Yg + (size_t)zj[i] * K + zc4[i]);

    const int swz = 2 * tx;

    for (int t = 0; t < NTILE; ++t) {
        const int b = t & 1;
        cp_wait0();
        __syncthreads();
        // transpose-store Z(t) with XOR swizzle (conflict-free k-pair reads)
#pragma unroll
        for (int i = 0; i < NZ4; ++i) {
            const int j = zj[i];
            const int c4 = zc4[i];
            float v[4] = {zr[i].x, zr[i].y, zr[i].z, zr[i].w};
#pragma unroll
            for (int u = 0; u < 4; ++u) {
                const int c = c4 + u;
                const int s = 2 * ((c >> SH) & 15);
                Zst[b][c][j ^ s] = v[u];
            }
        }
        if (t + 1 < NTILE) {
            const int j0n = (t + 1) * BK;
#pragma unroll
            for (int i = 0; i < 2; ++i) cp16(adst[b ^ 1][i], asrc[i] + j0n);
            cp_commit();
#pragma unroll
            for (int i = 0; i < NZ4; ++i)
                zr[i] = *(const float4*)(Yg + (size_t)(j0n + zj[i]) * K + zc4[i]);
        }
        __syncthreads();
        // inner product: both operands natural 8B k-pairs -> pure FFMA2
#pragma unroll
        for (int kk = 0; kk < BK; kk += 2) {
            const u64 a0 = *(const u64*)&As[b][ty * 2 + 0][kk];
            const u64 a1 = *(const u64*)&As[b][ty * 2 + 1][kk];
#pragma unroll
            for (int jc = 0; jc < TNc; ++jc) {
                const u64 z = *(const u64*)&Zst[b][tx * TNc + jc][kk ^ swz];
                fma2(acc[0][jc], a0, z);
                fma2(acc[1][jc], a1, z);
            }
        }
    }

    __syncthreads();
    const float d0 = g_d[g][rowBase + ty * 2 + 0];
    const float d1 = g_d[g][rowBase + ty * 2 + 1];

    if constexpr (KO == 0) {
        // column-sum partials of relu'd X (16 cols), for the mean.
        float* red = &As[0][0][0];
        float x0 = fmaxf(d0 * (lo32(acc[0][0]) + hi32(acc[0][0])), 0.0f);
        float x1 = fmaxf(d1 * (lo32(acc[1][0]) + hi32(acc[1][0])), 0.0f);
        red[ty * 16 + tx] = x0 + x1;
        __syncthreads();
#pragma unroll
        for (int off = 8; off >= 1; off >>= 1) {
            if (ty < off) red[ty * 16 + tx] += red[(ty + off) * 16 + tx];
            __syncthreads();
        }
        if (ty == 0) g_part[g][blockIdx.x][tx] = red[tx];
    } else {
        // fused: out = d .* (relu(d .* acc) @ W)
        float* Xs = &As[0][0][0];  // BM x K floats (fits in As)
#pragma unroll
        for (int jc = 0; jc < TNc; ++jc) {
            const int c = tx * TNc + jc;
            Xs[(ty * 2 + 0) * K + c] =
                fmaxf(d0 * (lo32(acc[0][jc]) + hi32(acc[0][jc])), 0.0f);
            Xs[(ty * 2 + 1) * K + c] =
                fmaxf(d1 * (lo32(acc[1][jc]) + hi32(acc[1][jc])), 0.0f);
        }
        float* Ws = &Zst[0][0][0];  // K*KO floats (fits)
        for (int i = tid; i < (K * KO) / 4; i += 256)
            ((float4*)Ws)[i] = ((const float4*)W)[i];
        __syncthreads();

        constexpr int CO = KO / 8;  // 4 or 2 cols per thread
        const int r = tid >> 3;
        const int co = (tid & 7) * CO;
        float oa[CO];
#pragma unroll
        for (int u = 0; u < CO; ++u) oa[u] = 0.0f;
#pragma unroll 8
        for (int t2 = 0; t2 < K; ++t2) {
            const float xv = Xs[r * K + t2];
#pragma unroll
            for (int u = 0; u < CO; ++u) oa[u] += xv * Ws[t2 * KO + co + u];
        }
        const float dr = g_d[g][rowBase + r];
        float* Og = SRC ? g_Y[g] : g_Zb[g];
        float* op = Og + (size_t)(rowBase + r) * KO + co;
#pragma unroll
        for (int u = 0; u < CO; ++u) oa[u] *= dr;
        if constexpr (CO == 4) {
            float4 o4 = {oa[0], oa[1], oa[2], oa[3]};
            *(float4*)op = o4;
        } else {
            float2 o2 = {oa[0], oa[1]};
            *(float2*)op = o2;
        }
    }
}

// ---------------------------------------------------------------------------
// reduce partials -> emb[32]; bilinear + linear + 3-layer MLP -> scalar.
__global__ void final_kernel(const float* __restrict__ cw1,
                             const float* __restrict__ cw2,
                             const float* __restrict__ cbias,
                             const float* __restrict__ fw1,
                             const float* __restrict__ fb1,
                             const float* __restrict__ fw2,
                             const float* __restrict__ fb2,
                             const float* __restrict__ fw3,
                             const float* __restrict__ fb3,
                             float* __restrict__ out) {
    __shared__ float emb[32];
    __shared__ float red[256];
    __shared__ float z[16];
    const int tid = threadIdx.x;
    const int g = tid >> 7;
    const int c = (tid >> 3) & 15;
    const int s = tid & 7;
    float sum = 0.0f;
    for (int b2 = s * 32; b2 < s * 32 + 32; ++b2) sum += g_part[g][b2][c];
    red[tid] = sum;
    __syncthreads();
    if (s == 0) {
        float tot = 0.0f;
        for (int u = 0; u < 8; ++u) tot += red[tid + u];
        emb[g * 16 + c] = tot * (1.0f / N);
    }
    __syncthreads();
    if (tid < 16) {
        const int k = tid;
        float r = 0.0f;
        for (int i = 0; i < 16; ++i) {
            float xi = emb[i];
            for (int j = 0; j < 16; ++j)
                r += xi * cw1[(i * 16 + j) * 16 + k] * emb[16 + j];
        }
        float p = 0.0f;
        for (int t = 0; t < 32; ++t) p += cw2[k * 32 + t] * emb[t];
        z[k] = fmaxf(r + p + cbias[k], 0.0f);
    }
    __syncthreads();
    if (tid == 0) {
        float z1[8];
        for (int a = 0; a < 8; ++a) {
            float s1 = fb1[a];
            for (int t = 0; t < 16; ++t) s1 += z[t] * fw1[a * 16 + t];
            z1[a] = fmaxf(s1, 0.0f);
        }
        float z2[4];
        for (int b = 0; b < 4; ++b) {
            float s2 = fb2[b];
            for (int a = 0; a < 8; ++a) s2 += z1[a] * fw2[b * 8 + a];
            z2[b] = fmaxf(s2, 0.0f);
        }
        float s3 = fb3[0];
        for (int b = 0; b < 4; ++b) s3 += z2[b] * fw3[b];
        out[0] = fmaxf(s3, 0.0f);
    }
}

// ---------------------------------------------------------------------------
extern "C" void kernel_launch(void* const* d_in, const int* in_sizes, int n_in,
                              void* d_out, int out_size) {
    (void)in_sizes; (void)n_in; (void)out_size;
    const float* A0 = (const float*)d_in[0];
    const float* Dm0 = (const float*)d_in[1];
    const float* H0 = (const float*)d_in[2];
    const float* A1 = (const float*)d_in[3];
    const float* Dm1 = (const float*)d_in[4];
    const float* H1 = (const float*)d_in[5];
    const float* W1 = (const float*)d_in[6];
    const float* W2 = (const float*)d_in[7];
    const float* W3 = (const float*)d_in[8];

    diag_kernel<<<dim3(32, 2), 256>>>(Dm0, Dm1);
    wmulH_kernel<<<dim3(N / BMH, 2), 256>>>(H0, H1, W1);
    prop_kernel<64, 32, 0><<<dim3(GRIDX, 2), 256>>>(A0, A1, W2);
    prop_kernel<32, 16, 1><<<dim3(GRIDX, 2), 256>>>(A0, A1, W3);
    prop_kernel<16, 0, 0><<<dim3(GRIDX, 2), 256>>>(A0, A1, nullptr);
    final_kernel<<<1, 256>>>((const float*)d_in[9], (const float*)d_in[10],
                             (const float*)d_in[11], (const float*)d_in[12],
                             (const float*)d_in[13], (const float*)d_in[14],
                             (const float*)d_in[15], (const float*)d_in[16],
                             (const float*)d_in[17], (float*)d_out);
}

// round 9
// speedup vs baseline: 2.0988x; 1.2390x over previous
#include <cuda_runtime.h>
#include <math.h>

// graphConvNet: two 8192-node GCNs + tiny head.
// (An@X)@W == An@(X@W);  An = d*A*d, d = rsqrt(diag(D)).
// All skinny operands kept TRANSPOSED in global (Yt[c][row]) so prop kernels
// read k-contiguous rows for BOTH operands -> pure k-packed fma.rn.f32x2
// inner loop (zero transpose, zero broadcast movs).

constexpr int N = 8192;
constexpr int BK = 32;
constexpr int SA = BK + 4;      // padded smem stride (36): conflict-free pattern
constexpr int NTILE = N / BK;   // 256

__device__ float g_d[2][N];
__device__ __align__(16) float g_Yt[2][64][N];  // stage-1 (64) / stage-3 (16) operand
__device__ __align__(16) float g_Zt[2][32][N];  // stage-2 operand
__device__ float g_part[2][64][16];

typedef unsigned long long u64;

__device__ __forceinline__ void fma2(u64& d, u64 a, u64 b) {
    asm("fma.rn.f32x2 %0, %1, %2, %0;" : "+l"(d) : "l"(a), "l"(b));
}
__device__ __forceinline__ float lo32(u64 v) { return __uint_as_float((unsigned)v); }
__device__ __forceinline__ float hi32(u64 v) { return __uint_as_float((unsigned)(v >> 32)); }

__device__ __forceinline__ void cp16(unsigned dst, const float* src) {
    asm volatile("cp.async.cg.shared.global [%0], [%1], 16;" :: "r"(dst), "l"(src));
}
__device__ __forceinline__ void cp_commit() { asm volatile("cp.async.commit_group;"); }
__device__ __forceinline__ void cp_wait0()  { asm volatile("cp.async.wait_group 0;"); }
__device__ __forceinline__ void cp_wait1()  { asm volatile("cp.async.wait_group 1;"); }

// ---------------------------------------------------------------------------
__global__ void diag_kernel(const float* __restrict__ D0,
                            const float* __restrict__ D1) {
    const int g = blockIdx.y;
    const float* Dm = g ? D1 : D0;
    int i = blockIdx.x * 256 + threadIdx.x;
    if (i < N) g_d[g][i] = rsqrtf(Dm[(size_t)i * (N + 1)]);
}

// ---------------------------------------------------------------------------
// g_Yt[g][c][r] = d[r] * (H[r,:] @ W1[:,c])     (transposed output)
constexpr int BMH = 16;
__global__ __launch_bounds__(256) void wmulH_kernel(const float* __restrict__ H0,
                                                    const float* __restrict__ H1,
                                                    const float* __restrict__ W1) {
    __shared__ float Hs[BMH][132];
    __shared__ float W1s[128 * 64];
    const int tid = threadIdx.x;
    const int g = blockIdx.y;
    const float* Hg = g ? H1 : H0;
    const int rowBase = blockIdx.x * BMH;

    for (int i = tid; i < 2048; i += 256)
        ((float4*)W1s)[i] = ((const float4*)W1)[i];
    for (int i = tid; i < 512; i += 256) {
        int r = i >> 5, c4 = (i & 31) * 4;
        *(float4*)&Hs[r][c4] = *(const float4*)(Hg + (size_t)(rowBase + r) * 128 + c4);
    }
    __syncthreads();

    const int r = tid & 15;
    const int co = (tid >> 4) * 4;
    float a0 = 0, a1 = 0, a2 = 0, a3 = 0;
#pragma unroll 16
    for (int t = 0; t < 128; ++t) {
        float x = Hs[r][t];
        float4 w = *(const float4*)&W1s[t * 64 + co];
        a0 += x * w.x; a1 += x * w.y; a2 += x * w.z; a3 += x * w.w;
    }
    float dr = g_d[g][rowBase + r];
    g_Yt[g][co + 0][rowBase + r] = dr * a0;
    g_Yt[g][co + 1][rowBase + r] = dr * a1;
    g_Yt[g][co + 2][rowBase + r] = dr * a2;
    g_Yt[g][co + 3][rowBase + r] = dr * a3;
}

// ---------------------------------------------------------------------------
// X = relu(d .* (A @ Zt^T))   (Zt is [BN][N], k-contiguous rows)
// KO>0: write Out_t[KO][N] = (d .* (X @ W))^T.   KO==0: column-sum partials.
template <int BN, int KO, int SRC>
__global__ __launch_bounds__(256, 2) void prop_kernel(
    const float* __restrict__ A0, const float* __restrict__ A1,
    const float* __restrict__ W) {
    constexpr int CT = (BN == 16) ? 4 : 8;   // col-threads
    constexpr int TN = BN / CT;              // cols per thread (interleaved)
    constexpr int RT = 256 / CT;             // row-threads
    constexpr int BM = RT * 2;               // rows per block (TM=2)
    constexpr int NCA = BM * 8 / 256;        // A 16B-chunks per thread
    constexpr int NCZ = (BN * 8) / 256;      // Z chunks per thread (0 -> half)

    __shared__ union {
        struct { float As[2][BM][SA]; float Zs[2][BN][SA]; } m;
        struct { float Xs[64][BN + 1]; float Ws[BN * 32]; } e;
        float red[64][16];
    } sm;

    const int tid = threadIdx.x;
    const int g = blockIdx.y;
    const int tx = tid % CT;
    const int ty = tid / CT;
    const int rowBase = blockIdx.x * BM;

    const float* __restrict__ Ag = g ? A1 : A0;
    const float* __restrict__ Zg = SRC ? &g_Zt[g][0][0] : &g_Yt[g][0][0];
    const float* Abase = Ag + (size_t)rowBase * N;

    // ---- loader setup (A: BM x 32 floats; Z: BN x 32 floats) ----
    const float* asrc[NCA > 0 ? NCA : 1];
    unsigned adst[2][NCA > 0 ? NCA : 1];
#pragma unroll
    for (int i = 0; i < NCA; ++i) {
        int c = i * 256 + tid;
        int r = c >> 3, c4 = (c & 7) * 4;
        asrc[i] = Abase + (size_t)r * N + c4;
#pragma unroll
        for (int b = 0; b < 2; ++b)
            adst[b][i] = (unsigned)__cvta_generic_to_shared(&sm.m.As[b][r][c4]);
    }
    constexpr int NZC = (NCZ > 0) ? NCZ : 1;
    const float* zsrc[NZC];
    unsigned zdst[2][NZC];
    bool zval = true;
    if constexpr (NCZ == 0) zval = (tid < BN * 8);
#pragma unroll
    for (int i = 0; i < NZC; ++i) {
        int c = i * 256 + tid;
        if constexpr (NCZ == 0) c = tid < BN * 8 ? tid : 0;
        int r = c >> 3, c4 = (c & 7) * 4;
        zsrc[i] = Zg + (size_t)r * N + c4;
#pragma unroll
        for (int b = 0; b < 2; ++b)
            zdst[b][i] = (unsigned)__cvta_generic_to_shared(&sm.m.Zs[b][r][c4]);
    }

    u64 acc[2][TN];
#pragma unroll
    for (int i = 0; i < 2; ++i)
#pragma unroll
        for (int j = 0; j < TN; ++j) acc[i][j] = 0ULL;

    // prologue: tile 0
#pragma unroll
    for (int i = 0; i < NCA; ++i) cp16(adst[0][i], asrc[i]);
#pragma unroll
    for (int i = 0; i < NZC; ++i) if (zval) cp16(zdst[0][i], zsrc[i]);
    cp_commit();

    for (int t = 0; t < NTILE; ++t) {
        const int b = t & 1;
        if (t + 1 < NTILE) {
            const int j0 = (t + 1) * BK;
#pragma unroll
            for (int i = 0; i < NCA; ++i) cp16(adst[b ^ 1][i], asrc[i] + j0);
#pragma unroll
            for (int i = 0; i < NZC; ++i) if (zval) cp16(zdst[b ^ 1][i], zsrc[i] + j0);
            cp_commit();
            cp_wait1();
        } else {
            cp_wait0();
        }
        __syncthreads();

#pragma unroll
        for (int kk = 0; kk < BK; kk += 2) {
            const u64 a0 = *(const u64*)&sm.m.As[b][ty][kk];
            const u64 a1 = *(const u64*)&sm.m.As[b][ty + RT][kk];
            u64 zv[TN];
#pragma unroll
            for (int j = 0; j < TN; ++j)
                zv[j] = *(const u64*)&sm.m.Zs[b][tx + CT * j][kk];
#pragma unroll
            for (int j = 0; j < TN; ++j) {
                fma2(acc[0][j], a0, zv[j]);
                fma2(acc[1][j], a1, zv[j]);
            }
        }
        __syncthreads();
    }

    const float d0 = g_d[g][rowBase + ty];
    const float d1 = g_d[g][rowBase + ty + RT];

    if constexpr (KO == 0) {
        // per-block column sums of relu'd X (16 cols)
        float s[TN];
#pragma unroll
        for (int j = 0; j < TN; ++j)
            s[j] = fmaxf(d0 * (lo32(acc[0][j]) + hi32(acc[0][j])), 0.0f) +
                   fmaxf(d1 * (lo32(acc[1][j]) + hi32(acc[1][j])), 0.0f);
        __syncthreads();
#pragma unroll
        for (int j = 0; j < TN; ++j) sm.red[ty][tx + CT * j] = s[j];
        __syncthreads();
#pragma unroll
        for (int off = 32; off >= 1; off >>= 1) {
            if (ty < off)
#pragma unroll
                for (int j = 0; j < TN; ++j)
                    sm.red[ty][tx + CT * j] += sm.red[ty + off][tx + CT * j];
            __syncthreads();
        }
        if (ty == 0)
#pragma unroll
            for (int j = 0; j < TN; ++j)
                g_part[g][blockIdx.x][tx + CT * j] = sm.red[0][tx + CT * j];
    } else {
        // fused: Out_t = (d .* (relu(d .* acc) @ W))^T
        __syncthreads();
#pragma unroll
        for (int j = 0; j < TN; ++j) {
            sm.e.Xs[ty][tx + CT * j] =
                fmaxf(d0 * (lo32(acc[0][j]) + hi32(acc[0][j])), 0.0f);
            sm.e.Xs[ty + RT][tx + CT * j] =
                fmaxf(d1 * (lo32(acc[1][j]) + hi32(acc[1][j])), 0.0f);
        }
        for (int i = tid; i < BN * KO / 4; i += 256)
            ((float4*)sm.e.Ws)[i] = ((const float4*)W)[i];
        __syncthreads();

        constexpr int CO = KO / 4;   // 8 or 4 cols per thread
        const int r2 = tid & 63;
        const int co = (tid >> 6) * CO;
        float oa[CO];
#pragma unroll
        for (int u = 0; u < CO; ++u) oa[u] = 0.0f;
#pragma unroll 8
        for (int t2 = 0; t2 < BN; ++t2) {
            const float xv = sm.e.Xs[r2][t2];
#pragma unroll
            for (int u = 0; u < CO; ++u) oa[u] += xv * sm.e.Ws[t2 * KO + co + u];
        }
        const float dr = g_d[g][rowBase + r2];
        float* Og = (KO == 32) ? &g_Zt[g][0][0] : &g_Yt[g][0][0];
#pragma unroll
        for (int u = 0; u < CO; ++u)
            Og[(size_t)(co + u) * N + rowBase + r2] = dr * oa[u];
    }
}

// ---------------------------------------------------------------------------
__global__ void final_kernel(const float* __restrict__ cw1,
                             const float* __restrict__ cw2,
                             const float* __restrict__ cbias,
                             const float* __restrict__ fw1,
                             const float* __restrict__ fb1,
                             const float* __restrict__ fw2,
                             const float* __restrict__ fb2,
                             const float* __restrict__ fw3,
                             const float* __restrict__ fb3,
                             float* __restrict__ out) {
    __shared__ float emb[32];
    __shared__ float red[256];
    __shared__ float z[16];
    const int tid = threadIdx.x;
    const int g = tid >> 7;
    const int c = (tid >> 3) & 15;
    const int s = tid & 7;
    float sum = 0.0f;
    for (int b2 = s * 8; b2 < s * 8 + 8; ++b2) sum += g_part[g][b2][c];
    red[tid] = sum;
    __syncthreads();
    if (s == 0) {
        float tot = 0.0f;
        for (int u = 0; u < 8; ++u) tot += red[tid + u];
        emb[g * 16 + c] = tot * (1.0f / N);
    }
    __syncthreads();
    if (tid < 16) {
        const int k = tid;
        float r = 0.0f;
        for (int i = 0; i < 16; ++i) {
            float xi = emb[i];
            for (int j = 0; j < 16; ++j)
                r += xi * cw1[(i * 16 + j) * 16 + k] * emb[16 + j];
        }
        float p = 0.0f;
        for (int t = 0; t < 32; ++t) p += cw2[k * 32 + t] * emb[t];
        z[k] = fmaxf(r + p + cbias[k], 0.0f);
    }
    __syncthreads();
    if (tid == 0) {
        float z1[8];
        for (int a = 0; a < 8; ++a) {
            float s1 = fb1[a];
            for (int t = 0; t < 16; ++t) s1 += z[t] * fw1[a * 16 + t];
            z1[a] = fmaxf(s1, 0.0f);
        }
        float z2[4];
        for (int b = 0; b < 4; ++b) {
            float s2 = fb2[b];
            for (int a = 0; a < 8; ++a) s2 += z1[a] * fw2[b * 8 + a];
            z2[b] = fmaxf(s2, 0.0f);
        }
        float s3 = fb3[0];
        for (int b = 0; b < 4; ++b) s3 += z2[b] * fw3[b];
        out[0] = fmaxf(s3, 0.0f);
    }
}

// ---------------------------------------------------------------------------
extern "C" void kernel_launch(void* const* d_in, const int* in_sizes, int n_in,
                              void* d_out, int out_size) {
    (void)in_sizes; (void)n_in; (void)out_size;
    const float* A0 = (const float*)d_in[0];
    const float* Dm0 = (const float*)d_in[1];
    const float* H0 = (const float*)d_in[2];
    const float* A1 = (const float*)d_in[3];
    const float* Dm1 = (const float*)d_in[4];
    const float* H1 = (const float*)d_in[5];
    const float* W1 = (const float*)d_in[6];
    const float* W2 = (const float*)d_in[7];
    const float* W3 = (const float*)d_in[8];

    diag_kernel<<<dim3(32, 2), 256>>>(Dm0, Dm1);
    wmulH_kernel<<<dim3(N / BMH, 2), 256>>>(H0, H1, W1);
    prop_kernel<64, 32, 0><<<dim3(N / 64, 2), 256>>>(A0, A1, W2);
    prop_kernel<32, 16, 1><<<dim3(N / 64, 2), 256>>>(A0, A1, W3);
    prop_kernel<16, 0, 0><<<dim3(N / 128, 2), 256>>>(A0, A1, nullptr);
    final_kernel<<<1, 256>>>((const float*)d_in[9], (const float*)d_in[10],
                             (const float*)d_in[11], (const float*)d_in[12],
                             (const float*)d_in[13], (const float*)d_in[14],
                             (const float*)d_in[15], (const float*)d_in[16],
                             (const float*)d_in[17], (float*)d_out);
}

// round 12
// speedup vs baseline: 3.1815x; 1.5158x over previous
#include <cuda_runtime.h>
#include <cuda_bf16.h>
#include <math.h>
#include <stdint.h>

// graphConvNet via mma.sync bf16 split-precision (sm_103-safe; no tcgen05).
// (An@X)@W == An@(X@W);  An = d*A*d, d = rsqrt(diag(D)).
// prop: X = relu(d .* (A @ Y)); A split on the fly to bf16 (hi,lo),
// Y pre-split/pre-swizzled by producers. 3 terms: hi*hi + hi*lo + lo*hi.

constexpr int N = 8192;
constexpr int BK = 64;          // k per tile (64 bf16 = 128B rows)
constexpr int NTILE = N / BK;   // 128
constexpr int BM = 128;         // rows per CTA

__device__ float g_d[2][N];
// Pre-swizzled bf16 B-operand tile images [graph][tile][n*64 + k]:
__device__ __align__(256) __nv_bfloat16 g_B1h[2][NTILE][64 * 64];
__device__ __align__(256) __nv_bfloat16 g_B1l[2][NTILE][64 * 64];
__device__ __align__(256) __nv_bfloat16 g_B2h[2][NTILE][32 * 64];
__device__ __align__(256) __nv_bfloat16 g_B2l[2][NTILE][32 * 64];
__device__ __align__(256) __nv_bfloat16 g_B3h[2][NTILE][16 * 64];
__device__ __align__(256) __nv_bfloat16 g_B3l[2][NTILE][16 * 64];
__device__ float g_part[2][64][16];

// ---------------------------------------------------------------- helpers
__device__ __forceinline__ unsigned cvta_s(const void* p) {
    return (unsigned)__cvta_generic_to_shared(p);
}
__device__ __forceinline__ void cp16(unsigned dst, const void* src) {
    asm volatile("cp.async.cg.shared.global [%0], [%1], 16;"
                 :: "r"(dst), "l"(src) : "memory");
}
__device__ __forceinline__ void cp_commit() { asm volatile("cp.async.commit_group;" ::: "memory"); }
__device__ __forceinline__ void cp_wait0()  { asm volatile("cp.async.wait_group 0;" ::: "memory"); }

__device__ __forceinline__ void ldm_x4(unsigned& r0, unsigned& r1, unsigned& r2,
                                       unsigned& r3, unsigned addr) {
    asm volatile("ldmatrix.sync.aligned.m8n8.x4.shared.b16 {%0,%1,%2,%3}, [%4];"
                 : "=r"(r0), "=r"(r1), "=r"(r2), "=r"(r3) : "r"(addr));
}
__device__ __forceinline__ void ldm_x4t(unsigned& r0, unsigned& r1, unsigned& r2,
                                        unsigned& r3, unsigned addr) {
    asm volatile("ldmatrix.sync.aligned.m8n8.x4.trans.shared.b16 {%0,%1,%2,%3}, [%4];"
                 : "=r"(r0), "=r"(r1), "=r"(r2), "=r"(r3) : "r"(addr));
}
__device__ __forceinline__ void mma_bf16(float* c, const unsigned* a,
                                         const unsigned* b) {
    asm volatile(
        "mma.sync.aligned.m16n8k16.row.col.f32.bf16.bf16.f32 "
        "{%0,%1,%2,%3}, {%4,%5,%6,%7}, {%8,%9}, {%0,%1,%2,%3};"
        : "+f"(c[0]), "+f"(c[1]), "+f"(c[2]), "+f"(c[3])
        : "r"(a[0]), "r"(a[1]), "r"(a[2]), "r"(a[3]), "r"(b[0]), "r"(b[1]));
}

// byte offset of bf16 element (n-row, k) in a tile image: 128B rows,
// 16B chunks XOR-swizzled by row (conflict-free ldmatrix + STS.128).
__device__ __forceinline__ unsigned swz_off(int row, int k) {
    return (unsigned)(row * 128 + (((k >> 3) ^ (row & 7)) << 4) + (k & 7) * 2);
}
// Split v into bf16 hi/lo, store swizzled into tile images.
__device__ __forceinline__ void store_split_swz(char* th, char* tl, int row,
                                                int k, float v) {
    __nv_bfloat16 h = __float2bfloat16(v);
    __nv_bfloat16 l = __float2bfloat16(v - __bfloat162float(h));
    unsigned sw = swz_off(row, k);
    *(__nv_bfloat16*)(th + sw) = h;
    *(__nv_bfloat16*)(tl + sw) = l;
}

// ---------------------------------------------------------------------------
__global__ void diag_kernel(const float* __restrict__ D0,
                            const float* __restrict__ D1) {
    const int g = blockIdx.y;
    const float* Dm = g ? D1 : D0;
    int i = blockIdx.x * 256 + threadIdx.x;
    if (i < N) g_d[g][i] = rsqrtf(Dm[(size_t)i * (N + 1)]);
}

// ---------------------------------------------------------------------------
// B1 = split/swizzled tile image of (d .* (H @ W1))^T   (64 n-rows)
constexpr int BMH = 16;
__global__ __launch_bounds__(256) void wmulH_kernel(const float* __restrict__ H0,
                                                    const float* __restrict__ H1,
                                                    const float* __restrict__ W1) {
    __shared__ float Hs[BMH][132];
    __shared__ float W1s[128 * 64];
    const int tid = threadIdx.x;
    const int g = blockIdx.y;
    const float* Hg = g ? H1 : H0;
    const int rowBase = blockIdx.x * BMH;

    for (int i = tid; i < 2048; i += 256)
        ((float4*)W1s)[i] = ((const float4*)W1)[i];
    for (int i = tid; i < 512; i += 256) {
        int r = i >> 5, c4 = (i & 31) * 4;
        *(float4*)&Hs[r][c4] = *(const float4*)(Hg + (size_t)(rowBase + r) * 128 + c4);
    }
    __syncthreads();

    const int r = tid & 15;
    const int co = (tid >> 4) * 4;
    float a[4] = {0, 0, 0, 0};
#pragma unroll 16
    for (int t = 0; t < 128; ++t) {
        float x = Hs[r][t];
        float4 w = *(const float4*)&W1s[t * 64 + co];
        a[0] += x * w.x; a[1] += x * w.y; a[2] += x * w.z; a[3] += x * w.w;
    }
    const int node = rowBase + r;
    const float dr = g_d[g][node];
    const int tb = node >> 6, kl = node & 63;
    char* th = (char*)g_B1h[g] + (size_t)tb * 8192;
    char* tl = (char*)g_B1l[g] + (size_t)tb * 8192;
#pragma unroll
    for (int u = 0; u < 4; ++u)
        store_split_swz(th, tl, co + u, kl, dr * a[u]);
}

// ---------------------------------------------------------------------------
// prop: S = A @ Y (mma.sync bf16 x3 terms); X = relu(d .* S).
// KO>0: next operand tiles = split((d .* (X @ W))^T).  KO==0: col-sum partials.
template <int BN, int KO, int STAGE>
__global__ __launch_bounds__(256, 1) void prop_kernel(
    const float* __restrict__ A0, const float* __restrict__ A1,
    const float* __restrict__ W) {
    constexpr int BROWB = BN * 128;            // bytes per B term tile
    constexpr int BUFB = 32768 + 2 * BROWB;    // Ah+Al+Bh+Bl
    constexpr int NT = BN / 8;                 // n8 tiles per warp

    extern __shared__ __align__(16) char dsm[];
    __shared__ float s_W[2048];
    __shared__ float s_red[16][16];

    const int tid = threadIdx.x;
    const int w = tid >> 5;          // warp: rows [16w, 16w+16)
    const int lane = tid & 31;
    const int g = blockIdx.y;
    const int rowBase = blockIdx.x * BM;
    const float* __restrict__ Ag = g ? A1 : A0;

    if (KO > 0)
        for (int i = tid; i < BN * KO; i += 256) s_W[i] = W[i];

    const char *bsh, *bsl;
    if (STAGE == 1)      { bsh = (const char*)g_B1h[g]; bsl = (const char*)g_B1l[g]; }
    else if (STAGE == 2) { bsh = (const char*)g_B2h[g]; bsl = (const char*)g_B2l[g]; }
    else                 { bsh = (const char*)g_B3h[g]; bsl = (const char*)g_B3l[g]; }

    // ---- A staging: thread owns row r, k-half kh (32 fp32 per tile) ----
    const int r = tid >> 1;
    const int kh = (tid & 1) * 32;
    const float* arow = Ag + (size_t)(rowBase + r) * N + kh;

    float4 rs[8];
    auto prefetchA = [&](int t) {
#pragma unroll
        for (int i = 0; i < 8; ++i)
            rs[i] = __ldg((const float4*)(arow + (size_t)t * BK) + i);
    };
    auto convertA = [&](int buf) {
        char* ah = dsm + buf * BUFB;
        char* al = ah + 16384;
#pragma unroll
        for (int gi = 0; gi < 4; ++gi) {
            float f[8];
            f[0] = rs[2 * gi].x;     f[1] = rs[2 * gi].y;
            f[2] = rs[2 * gi].z;     f[3] = rs[2 * gi].w;
            f[4] = rs[2 * gi + 1].x; f[5] = rs[2 * gi + 1].y;
            f[6] = rs[2 * gi + 1].z; f[7] = rs[2 * gi + 1].w;
            unsigned hw[4], lw[4];
#pragma unroll
            for (int p = 0; p < 4; ++p) {
                float a = f[2 * p], b = f[2 * p + 1];
                unsigned h;
                asm("cvt.rn.bf16x2.f32 %0, %1, %2;" : "=r"(h) : "f"(b), "f"(a));
                float ha = __uint_as_float(h << 16);
                float hb = __uint_as_float(h & 0xffff0000u);
                unsigned l;
                asm("cvt.rn.bf16x2.f32 %0, %1, %2;" : "=r"(l)
                    : "f"(b - hb), "f"(a - ha));
                hw[p] = h; lw[p] = l;
            }
            unsigned sw = swz_off(r, kh + gi * 8);
            *(uint4*)(ah + sw) = make_uint4(hw[0], hw[1], hw[2], hw[3]);
            *(uint4*)(al + sw) = make_uint4(lw[0], lw[1], lw[2], lw[3]);
        }
    };
    auto cpB = [&](int t, int buf) {
        char* bh = dsm + buf * BUFB + 32768;
        char* bl = bh + BROWB;
        const char* sh = bsh + (size_t)t * BROWB;
        const char* sl = bsl + (size_t)t * BROWB;
        for (int i = tid; i < BN * 8; i += 256) {
            cp16(cvta_s(bh + i * 16), sh + i * 16);
            cp16(cvta_s(bl + i * 16), sl + i * 16);
        }
        cp_commit();
    };

    float acc[NT][4];
#pragma unroll
    for (int n = 0; n < NT; ++n)
#pragma unroll
        for (int i = 0; i < 4; ++i) acc[n][i] = 0.0f;

    // ldmatrix base addresses (per lane)
    const int arow_l = 16 * w + (lane & 15);       // A frag row
    const int akoff = (lane >> 4) * 8;             // A frag k offset
    const int bnrow = (lane & 7) + ((lane >> 4) * 8);   // B frag n row (n16 grp)
    const int bkoff = ((lane >> 3) & 1) * 8;            // B frag k offset

    auto mmaTile = [&](int buf) {
        const char* ah = dsm + buf * BUFB;
        const char* al = ah + 16384;
        const char* bh = ah + 32768;
        const char* bl = bh + BROWB;
#pragma unroll
        for (int kc = 0; kc < 4; ++kc) {
            const int k0 = kc * 16;
            unsigned Ah[4], Al[4];
            ldm_x4(Ah[0], Ah[1], Ah[2], Ah[3],
                   cvta_s(ah + swz_off(arow_l, k0 + akoff)));
            ldm_x4(Al[0], Al[1], Al[2], Al[3],
                   cvta_s(al + swz_off(arow_l, k0 + akoff)));
#pragma unroll
            for (int n16 = 0; n16 < BN / 16; ++n16) {
                unsigned Bh[4], Bl[4];
                const unsigned boff = swz_off(n16 * 16 + bnrow, k0 + bkoff);
                ldm_x4t(Bh[0], Bh[1], Bh[2], Bh[3], cvta_s(bh + boff));
                ldm_x4t(Bl[0], Bl[1], Bl[2], Bl[3], cvta_s(bl + boff));
#pragma unroll
                for (int s = 0; s < 2; ++s) {
                    float* c = acc[n16 * 2 + s];
                    mma_bf16(c, Ah, Bh + 2 * s);
                    mma_bf16(c, Ah, Bl + 2 * s);
                    mma_bf16(c, Al, Bh + 2 * s);
                }
            }
        }
    };

    // ---- pipeline ----
    prefetchA(0);
    cpB(0, 0);
    convertA(0);
    prefetchA(1);
    cp_wait0();
    __syncthreads();

    for (int t = 0; t < NTILE; ++t) {
        const int b = t & 1, nb = b ^ 1;
        mmaTile(b);
        if (t + 1 < NTILE) {
            convertA(nb);
            cpB(t + 1, nb);
            if (t + 2 < NTILE) prefetchA(t + 2);
            cp_wait0();
            __syncthreads();
        }
    }
    __syncthreads();

    // ---- epilogue: X = relu(d .* acc) into smem ----
    constexpr int BNP = BN + 1;
    float* Xs = (float*)dsm;   // [128][BNP] (fits within buffer 0)
    {
        const int gq = lane >> 2, t2 = (lane & 3) * 2;
        const int r0 = 16 * w + gq;
        const float d0 = g_d[g][rowBase + r0];
        const float d1 = g_d[g][rowBase + r0 + 8];
#pragma unroll
        for (int n = 0; n < NT; ++n) {
            const int c0 = n * 8 + t2;
            Xs[r0 * BNP + c0]           = fmaxf(d0 * acc[n][0], 0.0f);
            Xs[r0 * BNP + c0 + 1]       = fmaxf(d0 * acc[n][1], 0.0f);
            Xs[(r0 + 8) * BNP + c0]     = fmaxf(d1 * acc[n][2], 0.0f);
            Xs[(r0 + 8) * BNP + c0 + 1] = fmaxf(d1 * acc[n][3], 0.0f);
        }
    }
    __syncthreads();

    if constexpr (KO == 0) {
        const int c = tid & 15, sgrp = tid >> 4;
        float sum = 0.0f;
#pragma unroll
        for (int rr = 0; rr < 8; ++rr) sum += Xs[(sgrp * 8 + rr) * BNP + c];
        s_red[sgrp][c] = sum;
        __syncthreads();
        if (tid < 16) {
            float tot = 0.0f;
#pragma unroll
            for (int s2 = 0; s2 < 16; ++s2) tot += s_red[s2][tid];
            g_part[g][blockIdx.x][tid] = tot;
        }
    } else {
        constexpr int CO = KO / 2;
        const int r2 = tid >> 1;
        const int co0 = (tid & 1) * CO;
        float oa[CO];
#pragma unroll
        for (int u = 0; u < CO; ++u) oa[u] = 0.0f;
#pragma unroll 8
        for (int c = 0; c < BN; ++c) {
            const float xv = Xs[r2 * BNP + c];
#pragma unroll
            for (int u = 0; u < CO; ++u) oa[u] += xv * s_W[c * KO + co0 + u];
        }
        const int node = rowBase + r2;
        const float dn = g_d[g][node];
        const int tb = node >> 6, kl = node & 63;
        char *th, *tl;
        if constexpr (KO == 32) {
            th = (char*)g_B2h[g] + (size_t)tb * 4096;
            tl = (char*)g_B2l[g] + (size_t)tb * 4096;
        } else {
            th = (char*)g_B3h[g] + (size_t)tb * 2048;
            tl = (char*)g_B3l[g] + (size_t)tb * 2048;
        }
#pragma unroll
        for (int u = 0; u < CO; ++u)
            store_split_swz(th, tl, co0 + u, kl, dn * oa[u]);
    }
}

// ---------------------------------------------------------------------------
__global__ void final_kernel(const float* __restrict__ cw1,
                             const float* __restrict__ cw2,
                             const float* __restrict__ cbias,
                             const float* __restrict__ fw1,
                             const float* __restrict__ fb1,
                             const float* __restrict__ fw2,
                             const float* __restrict__ fb2,
                             const float* __restrict__ fw3,
                             const float* __restrict__ fb3,
                             float* __restrict__ out) {
    __shared__ float emb[32];
    __shared__ float red[256];
    __shared__ float z[16];
    const int tid = threadIdx.x;
    const int g = tid >> 7;
    const int c = (tid >> 3) & 15;
    const int s = tid & 7;
    float sum = 0.0f;
    for (int b2 = s * 8; b2 < s * 8 + 8; ++b2) sum += g_part[g][b2][c];
    red[tid] = sum;
    __syncthreads();
    if (s == 0) {
        float tot = 0.0f;
        for (int u = 0; u < 8; ++u) tot += red[tid + u];
        emb[g * 16 + c] = tot * (1.0f / N);
    }
    __syncthreads();
    if (tid < 16) {
        const int k = tid;
        float r = 0.0f;
        for (int i = 0; i < 16; ++i) {
            float xi = emb[i];
            for (int j = 0; j < 16; ++j)
                r += xi * cw1[(i * 16 + j) * 16 + k] * emb[16 + j];
        }
        float p = 0.0f;
        for (int t = 0; t < 32; ++t) p += cw2[k * 32 + t] * emb[t];
        z[k] = fmaxf(r + p + cbias[k], 0.0f);
    }
    __syncthreads();
    if (tid == 0) {
        float z1[8];
        for (int a = 0; a < 8; ++a) {
            float s1 = fb1[a];
            for (int t = 0; t < 16; ++t) s1 += z[t] * fw1[a * 16 + t];
            z1[a] = fmaxf(s1, 0.0f);
        }
        float z2[4];
        for (int b = 0; b < 4; ++b) {
            float s2 = fb2[b];
            for (int a = 0; a < 8; ++a) s2 += z1[a] * fw2[b * 8 + a];
            z2[b] = fmaxf(s2, 0.0f);
        }
        float s3 = fb3[0];
        for (int b = 0; b < 4; ++b) s3 += z2[b] * fw3[b];
        out[0] = fmaxf(s3, 0.0f);
    }
}

// ---------------------------------------------------------------------------
extern "C" void kernel_launch(void* const* d_in, const int* in_sizes, int n_in,
                              void* d_out, int out_size) {
    (void)in_sizes; (void)n_in; (void)out_size;
    const float* A0 = (const float*)d_in[0];
    const float* Dm0 = (const float*)d_in[1];
    const float* H0 = (const float*)d_in[2];
    const float* A1 = (const float*)d_in[3];
    const float* Dm1 = (const float*)d_in[4];
    const float* H1 = (const float*)d_in[5];
    const float* W1 = (const float*)d_in[6];
    const float* W2 = (const float*)d_in[7];
    const float* W3 = (const float*)d_in[8];

    const int SM1 = 2 * (32768 + 2 * 64 * 128);  // 98304
    const int SM2 = 2 * (32768 + 2 * 32 * 128);  // 81920
    const int SM3 = 2 * (32768 + 2 * 16 * 128);  // 73728
    cudaFuncSetAttribute(prop_kernel<64, 32, 1>,
                         cudaFuncAttributeMaxDynamicSharedMemorySize, SM1);
    cudaFuncSetAttribute(prop_kernel<32, 16, 2>,
                         cudaFuncAttributeMaxDynamicSharedMemorySize, SM2);
    cudaFuncSetAttribute(prop_kernel<16, 0, 3>,
                         cudaFuncAttributeMaxDynamicSharedMemorySize, SM3);

    diag_kernel<<<dim3(32, 2), 256>>>(Dm0, Dm1);
    wmulH_kernel<<<dim3(N / BMH, 2), 256>>>(H0, H1, W1);
    prop_kernel<64, 32, 1><<<dim3(64, 2), 256, SM1>>>(A0, A1, W2);
    prop_kernel<32, 16, 2><<<dim3(64, 2), 256, SM2>>>(A0, A1, W3);
    prop_kernel<16, 0, 3><<<dim3(64, 2), 256, SM3>>>(A0, A1, nullptr);
    final_kernel<<<1, 256>>>((const float*)d_in[9], (const float*)d_in[10],
                             (const float*)d_in[11], (const float*)d_in[12],
                             (const float*)d_in[13], (const float*)d_in[14],
                             (const float*)d_in[15], (const float*)d_in[16],
                             (const float*)d_in[17], (float*)d_out);
}